// round 9
// baseline (speedup 1.0000x reference)
#include <cuda_runtime.h>
#include <math.h>
#include <stdint.h>

// ----------------------------------------------------------------------------
// NoiseRobustAttractorLayer — TF32 mma.sync, 3-stage cp.async rings.
// R9: BM=128 tiles for K2/K3/K5 (512-thread blocks) — halves weight L2
// traffic, smem write volume, and barrier count per output element.
// K4 stays BM=64 (LN over full N=512 caps registers).
// ----------------------------------------------------------------------------

#define T_TOK 65536
#define EPSV  1e-5f

__device__ float g_xn  [(size_t)T_TOK * 512];   // fp32 (residual)
__device__ float g_xnt [(size_t)T_TOK * 512];   // tf32-rounded (GEMM A)
__device__ float g_gate[(size_t)T_TOK * 4];
__device__ float g_h   [(size_t)T_TOK * 1024];  // tf32-rounded
__device__ float g_comb[(size_t)T_TOK * 512];   // tf32-rounded
__device__ float g_oact[(size_t)T_TOK * 512];   // tf32-rounded

__device__ float g_hW1t[4 * 512 * 256];
__device__ float g_hW2t[4 * 256 * 128];
__device__ float g_dynt[4 * 128 * 128];
__device__ float g_oW1t[512 * 512];
__device__ float g_oW2t[512 * 512];

__device__ __forceinline__ float warp_sum(float v) {
#pragma unroll
    for (int o = 16; o > 0; o >>= 1) v += __shfl_xor_sync(0xffffffffu, v, o);
    return v;
}
__device__ __forceinline__ float block_sum_128(float v, float* s) {
    v = warp_sum(v);
    int w = threadIdx.x >> 5;
    __syncthreads();
    if ((threadIdx.x & 31) == 0) s[w] = v;
    __syncthreads();
    return s[0] + s[1] + s[2] + s[3];
}
__device__ __forceinline__ float gelu_exact(float x) {
    return 0.5f * x * (1.0f + erff(x * 0.70710678118654752f));
}
__device__ __forceinline__ uint32_t f2tf(float x) {
    uint32_t r; asm("cvt.rna.tf32.f32 %0, %1;" : "=r"(r) : "f"(x)); return r;
}
__device__ __forceinline__ float f2tf_f(float x) {
    return __uint_as_float(f2tf(x));
}
__device__ __forceinline__ void mma_tf32(float c[4], const uint32_t a[4],
                                         uint32_t b0, uint32_t b1) {
    asm volatile(
        "mma.sync.aligned.m16n8k8.row.col.f32.tf32.tf32.f32 "
        "{%0,%1,%2,%3},{%4,%5,%6,%7},{%8,%9},{%0,%1,%2,%3};"
        : "+f"(c[0]), "+f"(c[1]), "+f"(c[2]), "+f"(c[3])
        : "r"(a[0]), "r"(a[1]), "r"(a[2]), "r"(a[3]), "r"(b0), "r"(b1));
}
__device__ __forceinline__ void cp16(void* s, const void* g) {
    uint32_t sa = (uint32_t)__cvta_generic_to_shared(s);
    asm volatile("cp.async.cg.shared.global [%0], [%1], 16;" :: "r"(sa), "l"(g));
}
#define CP_COMMIT()  asm volatile("cp.async.commit_group;")
#define CP_WAIT_1()  asm volatile("cp.async.wait_group 1;" ::: "memory")

// ============================================================================
// K0: weight pre-conversion fp32 -> tf32
// ============================================================================
__global__ void __launch_bounds__(256) k_prep(
    const float* __restrict__ hW1, const float* __restrict__ hW2,
    const float* __restrict__ dynm, const float* __restrict__ oW1,
    const float* __restrict__ oW2)
{
    int i = blockIdx.x * 256 + threadIdx.x;
    if (i < 524288)       g_hW1t[i]           = f2tf_f(hW1[i]);
    else if (i < 655360)  g_hW2t[i - 524288]  = f2tf_f(hW2[i - 524288]);
    else if (i < 720896)  g_dynt[i - 655360]  = f2tf_f(dynm[i - 655360]);
    else if (i < 983040)  g_oW1t[i - 720896]  = f2tf_f(oW1[i - 720896]);
    else if (i < 1245184) g_oW2t[i - 983040]  = f2tf_f(oW2[i - 983040]);
}

// ============================================================================
// K1: layernorm of x + gate logits (+ tf32 copy of xn)
// ============================================================================
__global__ void __launch_bounds__(128) k_ln_gate(
    const float* __restrict__ x, const float* __restrict__ ng,
    const float* __restrict__ nb, const float* __restrict__ gW,
    const float* __restrict__ gb)
{
    __shared__ float sred[4];
    __shared__ float sgW[2048];
    __shared__ float sng[512], snb[512];
    int tid = threadIdx.x;
    for (int i = tid; i < 2048; i += 128) sgW[i] = gW[i];
    for (int i = tid; i < 512; i += 128) { sng[i] = ng[i]; snb[i] = nb[i]; }
    __syncthreads();

    for (int t = blockIdx.x; t < T_TOK; t += gridDim.x) {
        const float* xr = x + (size_t)t * 512;
        float v[4];
#pragma unroll
        for (int j = 0; j < 4; j++) v[j] = xr[tid + 128 * j];
        float s = block_sum_128(v[0] + v[1] + v[2] + v[3], sred);
        float m = s * (1.0f / 512.0f);
        float q = 0.f;
#pragma unroll
        for (int j = 0; j < 4; j++) { float d = v[j] - m; q += d * d; }
        q = block_sum_128(q, sred);
        float rs = rsqrtf(q * (1.0f / 512.0f) + EPSV);
        float xn[4];
#pragma unroll
        for (int j = 0; j < 4; j++) {
            int i = tid + 128 * j;
            xn[j] = (v[j] - m) * rs * sng[i] + snb[i];
            g_xn [(size_t)t * 512 + i] = xn[j];
            g_xnt[(size_t)t * 512 + i] = f2tf_f(xn[j]);
        }
#pragma unroll
        for (int h = 0; h < 4; h++) {
            float p = 0.f;
#pragma unroll
            for (int j = 0; j < 4; j++) p += xn[j] * sgW[h * 512 + tid + 128 * j];
            p = block_sum_128(p, sred);
            if (tid == 0) g_gate[(size_t)t * 4 + h] = 1.0f / (1.0f + expf(-(p + gb[h])));
        }
    }
}

// ============================================================================
// K2: h = gelu(LN(xn @ hW1[h] + hb1)).  BM=128, BN=256, block 512 (warps 4x4).
// smem: As 3*10240 | Bs 3*16896 | sB sG sBt | ps pq = 88576 B
// ============================================================================
#define K2_SMEM 88576
__global__ void __launch_bounds__(512) k_head1_mma(
    const float* __restrict__ hb1,
    const float* __restrict__ hlg, const float* __restrict__ hlb)
{
    extern __shared__ __align__(16) char dsm[];
    uint32_t* As = (uint32_t*)dsm;                 // 30720 (3*128*20)
    uint32_t* Bs = (uint32_t*)(dsm + 30720);       // 50688 (3*16*264)
    float* sB  = (float*)(dsm + 81408);
    float* sG  = (float*)(dsm + 82432);
    float* sBt = (float*)(dsm + 83456);
    float* ps  = (float*)(dsm + 84480);            // 128*4
    float* pq  = (float*)(dsm + 86528);            // 128*4

    const int h = blockIdx.y;
    const int t0 = blockIdx.x * 128;
    const int tid = threadIdx.x, w = tid >> 5, l = tid & 31;
    const int wr = w >> 2, wc = w & 3, g = l >> 2, tig = l & 3;

    if (tid < 256) { sB[tid] = hb1[h * 256 + tid]; sG[tid] = hlg[h * 256 + tid]; sBt[tid] = hlb[h * 256 + tid]; }

    float acc[2][8][4];
#pragma unroll
    for (int mt = 0; mt < 2; mt++)
#pragma unroll
        for (int nt = 0; nt < 8; nt++)
#pragma unroll
            for (int i = 0; i < 4; i++) acc[mt][nt][i] = 0.f;

    const float* Wp = g_hW1t + (size_t)h * 512 * 256;
    const int ar = tid >> 2, ac4 = (tid & 3) * 4;
    const float* Ap = g_xnt + (size_t)(t0 + ar) * 512 + ac4;

    auto load_stage = [&](int s, int k0) {
        cp16(&As[s * 2560 + ar * 20 + ac4], Ap + k0);
#pragma unroll
        for (int i = 0; i < 2; i++) {
            int idx = tid + 512 * i;
            int kk = idx >> 6, c4 = (idx & 63) * 4;
            cp16(&Bs[s * 4224 + kk * 264 + c4], Wp + (size_t)(k0 + kk) * 256 + c4);
        }
    };

    load_stage(0, 0);  CP_COMMIT();
    load_stage(1, 16); CP_COMMIT();
    int cur = 0;
    for (int it = 0; it < 32; it++) {
        CP_WAIT_1();
        __syncthreads();
        if (it + 2 < 32) load_stage((cur + 2 >= 3) ? cur - 1 : cur + 2, (it + 2) * 16);
        CP_COMMIT();
        const uint32_t* Ab = &As[cur * 2560];
        const uint32_t* Bb = &Bs[cur * 4224];
#pragma unroll
        for (int ks = 0; ks < 16; ks += 8) {
            uint32_t af[2][4];
#pragma unroll
            for (int mt = 0; mt < 2; mt++) {
                int rb = (wr * 32 + mt * 16 + g) * 20 + ks;
                af[mt][0] = Ab[rb + tig];       af[mt][1] = Ab[rb + 160 + tig];
                af[mt][2] = Ab[rb + tig + 4];   af[mt][3] = Ab[rb + 160 + tig + 4];
            }
#pragma unroll
            for (int nt = 0; nt < 8; nt++) {
                int cb = wc * 64 + nt * 8 + g;
                uint32_t b0 = Bb[(ks + tig) * 264 + cb];
                uint32_t b1 = Bb[(ks + tig + 4) * 264 + cb];
                mma_tf32(acc[0][nt], af[0], b0, b1);
                mma_tf32(acc[1][nt], af[1], b0, b1);
            }
        }
        cur = (cur + 1 == 3) ? 0 : cur + 1;
    }
    __syncthreads();

    // epilogue: bias + LN(256) + gelu ; store tf32-rounded
    float rsm[4] = {0, 0, 0, 0}, rsq[4] = {0, 0, 0, 0};
#pragma unroll
    for (int mt = 0; mt < 2; mt++)
#pragma unroll
        for (int nt = 0; nt < 8; nt++) {
            int c0 = wc * 64 + nt * 8 + 2 * tig;
            float v0 = acc[mt][nt][0] + sB[c0], v1 = acc[mt][nt][1] + sB[c0 + 1];
            float v2 = acc[mt][nt][2] + sB[c0], v3 = acc[mt][nt][3] + sB[c0 + 1];
            acc[mt][nt][0] = v0; acc[mt][nt][1] = v1; acc[mt][nt][2] = v2; acc[mt][nt][3] = v3;
            rsm[mt * 2 + 0] += v0 + v1; rsq[mt * 2 + 0] += v0 * v0 + v1 * v1;
            rsm[mt * 2 + 1] += v2 + v3; rsq[mt * 2 + 1] += v2 * v2 + v3 * v3;
        }
#pragma unroll
    for (int off = 1; off < 4; off <<= 1)
#pragma unroll
        for (int q = 0; q < 4; q++) {
            rsm[q] += __shfl_xor_sync(0xffffffffu, rsm[q], off);
            rsq[q] += __shfl_xor_sync(0xffffffffu, rsq[q], off);
        }
    if (tig == 0) {
#pragma unroll
        for (int q = 0; q < 4; q++) {
            int row = wr * 32 + (q >> 1) * 16 + (q & 1) * 8 + g;
            ps[row * 4 + wc] = rsm[q]; pq[row * 4 + wc] = rsq[q];
        }
    }
    __syncthreads();
    float mv[4], rv[4];
#pragma unroll
    for (int q = 0; q < 4; q++) {
        int row = wr * 32 + (q >> 1) * 16 + (q & 1) * 8 + g;
        float s  = ps[row * 4 + 0] + ps[row * 4 + 1] + ps[row * 4 + 2] + ps[row * 4 + 3];
        float s2 = pq[row * 4 + 0] + pq[row * 4 + 1] + pq[row * 4 + 2] + pq[row * 4 + 3];
        float m = s * (1.f / 256.f);
        float var = s2 * (1.f / 256.f) - m * m;
        mv[q] = m; rv[q] = rsqrtf(var + EPSV);
    }
#pragma unroll
    for (int mt = 0; mt < 2; mt++)
#pragma unroll
        for (int nt = 0; nt < 8; nt++) {
            int c0 = wc * 64 + nt * 8 + 2 * tig;
            int q0 = mt * 2;
            int row0 = t0 + wr * 32 + mt * 16 + g;
            float u0 = gelu_exact((acc[mt][nt][0] - mv[q0]) * rv[q0] * sG[c0] + sBt[c0]);
            float u1 = gelu_exact((acc[mt][nt][1] - mv[q0]) * rv[q0] * sG[c0 + 1] + sBt[c0 + 1]);
            *(float2*)&g_h[(size_t)row0 * 1024 + h * 256 + c0] =
                make_float2(f2tf_f(u0), f2tf_f(u1));
            float u2 = gelu_exact((acc[mt][nt][2] - mv[q0 + 1]) * rv[q0 + 1] * sG[c0] + sBt[c0]);
            float u3 = gelu_exact((acc[mt][nt][3] - mv[q0 + 1]) * rv[q0 + 1] * sG[c0 + 1] + sBt[c0 + 1]);
            *(float2*)&g_h[(size_t)(row0 + 8) * 1024 + h * 256 + c0] =
                make_float2(f2tf_f(u2), f2tf_f(u3));
        }
}

// ============================================================================
// K3: BM=128 fused head-2. block 512 (warps 4x4), warp tile 32x32.
// smem: As 30720 | Bs 26112 | Ss 67584 | At 4096 | AtT 4096 | Sa 4096 |
//       Sw 4096 | s2p 2048 | a2s 32 | Sgt 512 = 143392 B
// ============================================================================
#define K3_SMEM 143392
__global__ void __launch_bounds__(512) k_head2_mma(
    const float* __restrict__ hb2, const float* __restrict__ attr)
{
    extern __shared__ __align__(16) char dsm[];
    uint32_t* As  = (uint32_t*)dsm;                // 30720 (3*128*20)
    uint32_t* Bs  = (uint32_t*)(dsm + 30720);      // 26112 (3*16*136)
    float*    Ss  = (float*)(dsm + 56832);         // 67584 (128*132)
    float*    At  = (float*)(dsm + 124416);        //  4096 (8*128)
    uint32_t* AtT = (uint32_t*)(dsm + 128512);     //  4096 (128*8)
    float*    Sa  = (float*)(dsm + 132608);        //  4096 (128*8)
    float*    Sw  = (float*)(dsm + 136704);        //  4096 (128*8)
    float*    s2p = (float*)(dsm + 140800);        //  2048 (128*4)
    float*    a2s = (float*)(dsm + 142848);        //    32
    float*    Sgt = (float*)(dsm + 142880);        //   512

    const int h = blockIdx.y;
    const int t0 = blockIdx.x * 128;
    const int tid = threadIdx.x, w = tid >> 5, l = tid & 31;
    const int wr = w >> 2, wc = w & 3, g = l >> 2, tig = l & 3;

    if (tid < 256) {
        float4 v = *(const float4*)(attr + (size_t)h * 1024 + tid * 4);
        *(float4*)&At[tid * 4] = v;
        int a0 = tid >> 5, d0 = (tid & 31) * 4;
        AtT[(d0 + 0) * 8 + a0] = f2tf(v.x);
        AtT[(d0 + 1) * 8 + a0] = f2tf(v.y);
        AtT[(d0 + 2) * 8 + a0] = f2tf(v.z);
        AtT[(d0 + 3) * 8 + a0] = f2tf(v.w);
    }

    // ---- phase 1: state = h @ hW2[h] ----
    float acc[2][4][4];
#pragma unroll
    for (int mt = 0; mt < 2; mt++)
#pragma unroll
        for (int nt = 0; nt < 4; nt++)
#pragma unroll
            for (int i = 0; i < 4; i++) acc[mt][nt][i] = 0.f;

    const int ar = tid >> 2, ac4 = (tid & 3) * 4;
    const float* Ap = g_h + (size_t)(t0 + ar) * 1024 + h * 256 + ac4;
    const float* Wp = g_hW2t + (size_t)h * 256 * 128;
    const int bkk = tid >> 5, bc4 = (tid & 31) * 4;

    auto load_stage1 = [&](int s, int k0) {
        cp16(&As[s * 2560 + ar * 20 + ac4], Ap + k0);
        cp16(&Bs[s * 2176 + bkk * 136 + bc4], Wp + (size_t)(k0 + bkk) * 128 + bc4);
    };

    load_stage1(0, 0);  CP_COMMIT();
    load_stage1(1, 16); CP_COMMIT();
    __syncthreads();
    if (tid < 8) {
        float q = 0.f;
#pragma unroll
        for (int k = 0; k < 128; k++) q += At[tid * 128 + k] * At[tid * 128 + k];
        a2s[tid] = q;
    }

    int cur = 0;
    for (int it = 0; it < 16; it++) {
        CP_WAIT_1();
        __syncthreads();
        if (it + 2 < 16) load_stage1((cur + 2 >= 3) ? cur - 1 : cur + 2, (it + 2) * 16);
        CP_COMMIT();
        const uint32_t* Ab = &As[cur * 2560];
        const uint32_t* Bb = &Bs[cur * 2176];
#pragma unroll
        for (int ks = 0; ks < 16; ks += 8) {
            uint32_t af[2][4];
#pragma unroll
            for (int mt = 0; mt < 2; mt++) {
                int rb = (wr * 32 + mt * 16 + g) * 20 + ks;
                af[mt][0] = Ab[rb + tig];       af[mt][1] = Ab[rb + 160 + tig];
                af[mt][2] = Ab[rb + tig + 4];   af[mt][3] = Ab[rb + 160 + tig + 4];
            }
#pragma unroll
            for (int nt = 0; nt < 4; nt++) {
                int cb = wc * 32 + nt * 8 + g;
                uint32_t b0 = Bb[(ks + tig) * 136 + cb];
                uint32_t b1 = Bb[(ks + tig + 4) * 136 + cb];
                mma_tf32(acc[0][nt], af[0], b0, b1);
                mma_tf32(acc[1][nt], af[1], b0, b1);
            }
        }
        cur = (cur + 1 == 3) ? 0 : cur + 1;
    }
    __syncthreads();   // all warps done before phase-2 prefetch reuses Bs

    // prefetch dynamics stages 0,1
    const float* Dp = g_dynt + (size_t)h * 128 * 128;
    auto load_stage2 = [&](int s, int k0) {
        cp16(&Bs[s * 2176 + bkk * 136 + bc4], Dp + (size_t)(k0 + bkk) * 128 + bc4);
    };
    load_stage2(0, 0);  CP_COMMIT();
    load_stage2(1, 16); CP_COMMIT();

    // epilogue 1: bias, tf32-round, store Ss, ||s||^2 partials
    {
        float rq[4] = {0, 0, 0, 0};
#pragma unroll
        for (int mt = 0; mt < 2; mt++)
#pragma unroll
            for (int nt = 0; nt < 4; nt++) {
                int c0 = wc * 32 + nt * 8 + 2 * tig;
                int row = wr * 32 + mt * 16 + g;
                float b0v = hb2[h * 128 + c0], b1v = hb2[h * 128 + c0 + 1];
                float v0 = f2tf_f(acc[mt][nt][0] + b0v);
                float v1 = f2tf_f(acc[mt][nt][1] + b1v);
                float v2 = f2tf_f(acc[mt][nt][2] + b0v);
                float v3 = f2tf_f(acc[mt][nt][3] + b1v);
                Ss[row * 132 + c0]           = v0;
                Ss[row * 132 + c0 + 1]       = v1;
                Ss[(row + 8) * 132 + c0]     = v2;
                Ss[(row + 8) * 132 + c0 + 1] = v3;
                rq[mt * 2 + 0] += v0 * v0 + v1 * v1;
                rq[mt * 2 + 1] += v2 * v2 + v3 * v3;
            }
#pragma unroll
        for (int off = 1; off < 4; off <<= 1)
#pragma unroll
            for (int q = 0; q < 4; q++)
                rq[q] += __shfl_xor_sync(0xffffffffu, rq[q], off);
        if (tig == 0) {
#pragma unroll
            for (int q = 0; q < 4; q++) {
                int row = wr * 32 + (q >> 1) * 16 + (q & 1) * 8 + g;
                s2p[row * 4 + wc] = rq[q];
            }
        }
    }
    __syncthreads();

    // ---- phase 2: [dyn | sa] = state @ [dynamics[h] | attrT] ----
    float dcc[2][4][4];
    float scc[2][4];
#pragma unroll
    for (int mt = 0; mt < 2; mt++) {
#pragma unroll
        for (int nt = 0; nt < 4; nt++)
#pragma unroll
            for (int i = 0; i < 4; i++) dcc[mt][nt][i] = 0.f;
#pragma unroll
        for (int i = 0; i < 4; i++) scc[mt][i] = 0.f;
    }

    cur = 0;
    for (int it = 0; it < 8; it++) {
        CP_WAIT_1();
        __syncthreads();
        if (it + 2 < 8) load_stage2((cur + 2 >= 3) ? cur - 1 : cur + 2, (it + 2) * 16);
        CP_COMMIT();
        const uint32_t* Bb = &Bs[cur * 2176];
        const int kbase = it * 16;
#pragma unroll
        for (int ks = 0; ks < 16; ks += 8) {
            uint32_t af[2][4];
#pragma unroll
            for (int mt = 0; mt < 2; mt++) {
                int rb = (wr * 32 + mt * 16 + g) * 132 + kbase + ks;
                af[mt][0] = __float_as_uint(Ss[rb + tig]);
                af[mt][1] = __float_as_uint(Ss[rb + 8 * 132 + tig]);
                af[mt][2] = __float_as_uint(Ss[rb + tig + 4]);
                af[mt][3] = __float_as_uint(Ss[rb + 8 * 132 + tig + 4]);
            }
#pragma unroll
            for (int nt = 0; nt < 4; nt++) {
                int cb = wc * 32 + nt * 8 + g;
                uint32_t b0 = Bb[(ks + tig) * 136 + cb];
                uint32_t b1 = Bb[(ks + tig + 4) * 136 + cb];
                mma_tf32(dcc[0][nt], af[0], b0, b1);
                mma_tf32(dcc[1][nt], af[1], b0, b1);
            }
            uint32_t b0s = AtT[(kbase + ks + tig) * 8 + g];
            uint32_t b1s = AtT[(kbase + ks + tig + 4) * 8 + g];
            mma_tf32(scc[0], af[0], b0s, b1s);
            mma_tf32(scc[1], af[1], b0s, b1s);
        }
        cur = (cur + 1 == 3) ? 0 : cur + 1;
    }
    __syncthreads();

    if (wc == 0) {
#pragma unroll
        for (int mt = 0; mt < 2; mt++) {
            int row = wr * 32 + mt * 16 + g;
            Sa[row * 8 + 2 * tig]           = scc[mt][0];
            Sa[row * 8 + 2 * tig + 1]       = scc[mt][1];
            Sa[(row + 8) * 8 + 2 * tig]     = scc[mt][2];
            Sa[(row + 8) * 8 + 2 * tig + 1] = scc[mt][3];
        }
    }
    __syncthreads();

    const float invs = 0.08838834764831845f;  // 1/sqrt(128)
    if (tid < 128) {
        int row = tid;
        float s2 = s2p[row * 4 + 0] + s2p[row * 4 + 1] + s2p[row * 4 + 2] + s2p[row * 4 + 3];
        float lgt[8], mx = -1e30f;
#pragma unroll
        for (int a = 0; a < 8; a++) {
            float dd = sqrtf(fmaxf(s2 + a2s[a] - 2.0f * Sa[row * 8 + a], 0.0f));
            lgt[a] = -dd * invs;
            mx = fmaxf(mx, lgt[a]);
        }
        float e[8], se = 0.f;
#pragma unroll
        for (int a = 0; a < 8; a++) { e[a] = expf(lgt[a] - mx); se += e[a]; }
        float ise = 1.0f / se;
#pragma unroll
        for (int a = 0; a < 8; a++) Sw[row * 8 + a] = e[a] * ise;
        Sgt[row] = 0.1f * g_gate[(size_t)(t0 + row) * 4 + h];
    }
    __syncthreads();

#pragma unroll
    for (int mt = 0; mt < 2; mt++)
#pragma unroll
        for (int nt = 0; nt < 4; nt++) {
            int c0 = wc * 32 + nt * 8 + 2 * tig;
#pragma unroll
            for (int half = 0; half < 2; half++) {
                int row = wr * 32 + mt * 16 + g + 8 * half;
                float gt = Sgt[row];
                float sv0 = Ss[row * 132 + c0];
                float sv1 = Ss[row * 132 + c0 + 1];
                float ai0 = 0.f, ai1 = 0.f;
#pragma unroll
                for (int a = 0; a < 8; a++) {
                    float wgt = Sw[row * 8 + a];
                    ai0 += wgt * At[a * 128 + c0];
                    ai1 += wgt * At[a * 128 + c0 + 1];
                }
                float dv0 = dcc[mt][nt][2 * half + 0];
                float dv1 = dcc[mt][nt][2 * half + 1];
                float o0 = f2tf_f(sv0 + gt * (ai0 - sv0 + tanhf(dv0)));
                float o1 = f2tf_f(sv1 + gt * (ai1 - sv1 + tanhf(dv1)));
                *(float2*)&g_comb[(size_t)(t0 + row) * 512 + h * 128 + c0] =
                    make_float2(o0, o1);
            }
        }
}

// ============================================================================
// K4: o1 = gelu(LN(comb @ oW1 + ob1)).  BM=64, BN=512, block 512, 3-stage.
// (unchanged from R8 — LN over full 512 width requires BN=512.)
// ============================================================================
#define K4_SMEM 125440
__global__ void __launch_bounds__(512) k_out1_mma(
    const float* __restrict__ ob1,
    const float* __restrict__ olg, const float* __restrict__ olb)
{
    extern __shared__ __align__(16) char dsm[];
    uint32_t* As = (uint32_t*)dsm;                 // 15360 (3*64*20)
    uint32_t* Bs = (uint32_t*)(dsm + 15360);       // 99840 (3*16*520)
    float* sB  = (float*)(dsm + 115200);
    float* sG  = (float*)(dsm + 117248);
    float* sBt = (float*)(dsm + 119296);
    float* ps  = (float*)(dsm + 121344);           // 64*8
    float* pq  = (float*)(dsm + 123392);

    const int t0 = blockIdx.x * 64;
    const int tid = threadIdx.x, w = tid >> 5, l = tid & 31;
    const int wr = w >> 3, wc = w & 7, g = l >> 2, tig = l & 3;

    sB[tid] = ob1[tid]; sG[tid] = olg[tid]; sBt[tid] = olb[tid];

    float acc[2][8][4];
#pragma unroll
    for (int mt = 0; mt < 2; mt++)
#pragma unroll
        for (int nt = 0; nt < 8; nt++)
#pragma unroll
            for (int i = 0; i < 4; i++) acc[mt][nt][i] = 0.f;

    const int ar = tid >> 2, ac4 = (tid & 3) * 4;
    const float* Ap = g_comb + (size_t)(t0 + (ar & 63)) * 512 + ac4;

    auto load_stage = [&](int s, int k0) {
        if (tid < 256) cp16(&As[s * 1280 + ar * 20 + ac4], Ap + k0);
#pragma unroll
        for (int i = 0; i < 4; i++) {
            int idx = tid + 512 * i;
            int kk = idx >> 7, c4 = (idx & 127) * 4;
            cp16(&Bs[s * 8320 + kk * 520 + c4], g_oW1t + (size_t)(k0 + kk) * 512 + c4);
        }
    };

    load_stage(0, 0);  CP_COMMIT();
    load_stage(1, 16); CP_COMMIT();
    int cur = 0;
    for (int it = 0; it < 32; it++) {
        CP_WAIT_1();
        __syncthreads();
        if (it + 2 < 32) load_stage((cur + 2 >= 3) ? cur - 1 : cur + 2, (it + 2) * 16);
        CP_COMMIT();
        const uint32_t* Ab = &As[cur * 1280];
        const uint32_t* Bb = &Bs[cur * 8320];
#pragma unroll
        for (int ks = 0; ks < 16; ks += 8) {
            uint32_t af[2][4];
#pragma unroll
            for (int mt = 0; mt < 2; mt++) {
                int rb = (wr * 32 + mt * 16 + g) * 20 + ks;
                af[mt][0] = Ab[rb + tig];       af[mt][1] = Ab[rb + 160 + tig];
                af[mt][2] = Ab[rb + tig + 4];   af[mt][3] = Ab[rb + 160 + tig + 4];
            }
#pragma unroll
            for (int nt = 0; nt < 8; nt++) {
                int cb = wc * 64 + nt * 8 + g;
                uint32_t b0 = Bb[(ks + tig) * 520 + cb];
                uint32_t b1 = Bb[(ks + tig + 4) * 520 + cb];
                mma_tf32(acc[0][nt], af[0], b0, b1);
                mma_tf32(acc[1][nt], af[1], b0, b1);
            }
        }
        cur = (cur + 1 == 3) ? 0 : cur + 1;
    }
    __syncthreads();

    float rsm[4] = {0, 0, 0, 0}, rsq[4] = {0, 0, 0, 0};
#pragma unroll
    for (int mt = 0; mt < 2; mt++)
#pragma unroll
        for (int nt = 0; nt < 8; nt++) {
            int c0 = wc * 64 + nt * 8 + 2 * tig;
            float v0 = acc[mt][nt][0] + sB[c0], v1 = acc[mt][nt][1] + sB[c0 + 1];
            float v2 = acc[mt][nt][2] + sB[c0], v3 = acc[mt][nt][3] + sB[c0 + 1];
            acc[mt][nt][0] = v0; acc[mt][nt][1] = v1; acc[mt][nt][2] = v2; acc[mt][nt][3] = v3;
            rsm[mt * 2 + 0] += v0 + v1; rsq[mt * 2 + 0] += v0 * v0 + v1 * v1;
            rsm[mt * 2 + 1] += v2 + v3; rsq[mt * 2 + 1] += v2 * v2 + v3 * v3;
        }
#pragma unroll
    for (int off = 1; off < 4; off <<= 1)
#pragma unroll
        for (int q = 0; q < 4; q++) {
            rsm[q] += __shfl_xor_sync(0xffffffffu, rsm[q], off);
            rsq[q] += __shfl_xor_sync(0xffffffffu, rsq[q], off);
        }
    if (tig == 0) {
#pragma unroll
        for (int q = 0; q < 4; q++) {
            int row = wr * 32 + (q >> 1) * 16 + (q & 1) * 8 + g;
            ps[row * 8 + wc] = rsm[q]; pq[row * 8 + wc] = rsq[q];
        }
    }
    __syncthreads();
    float mv[4], rv[4];
#pragma unroll
    for (int q = 0; q < 4; q++) {
        int row = wr * 32 + (q >> 1) * 16 + (q & 1) * 8 + g;
        float s = 0.f, s2 = 0.f;
#pragma unroll
        for (int j = 0; j < 8; j++) { s += ps[row * 8 + j]; s2 += pq[row * 8 + j]; }
        float m = s * (1.f / 512.f);
        float var = s2 * (1.f / 512.f) - m * m;
        mv[q] = m; rv[q] = rsqrtf(var + EPSV);
    }
#pragma unroll
    for (int mt = 0; mt < 2; mt++)
#pragma unroll
        for (int nt = 0; nt < 8; nt++) {
            int c0 = wc * 64 + nt * 8 + 2 * tig;
            int q0 = mt * 2;
            int row0 = t0 + wr * 32 + mt * 16 + g;
            float u0 = gelu_exact((acc[mt][nt][0] - mv[q0]) * rv[q0] * sG[c0] + sBt[c0]);
            float u1 = gelu_exact((acc[mt][nt][1] - mv[q0]) * rv[q0] * sG[c0 + 1] + sBt[c0 + 1]);
            *(float2*)&g_oact[(size_t)row0 * 512 + c0] = make_float2(f2tf_f(u0), f2tf_f(u1));
            float u2 = gelu_exact((acc[mt][nt][2] - mv[q0 + 1]) * rv[q0 + 1] * sG[c0] + sBt[c0]);
            float u3 = gelu_exact((acc[mt][nt][3] - mv[q0 + 1]) * rv[q0 + 1] * sG[c0 + 1] + sBt[c0 + 1]);
            *(float2*)&g_oact[(size_t)(row0 + 8) * 512 + c0] = make_float2(f2tf_f(u2), f2tf_f(u3));
        }
}

// ============================================================================
// K5: out = xn + oact @ oW2 + ob2.  BM=128, BN=256, block 512 (warps 4x4).
// grid (T/128, 2), blockIdx.y selects column half.
// smem: As 30720 | Bs 50688 | sB 1024 = 82432 B
// ============================================================================
#define K5_SMEM 82432
__global__ void __launch_bounds__(512) k_out2_mma(
    const float* __restrict__ ob2, float* __restrict__ out)
{
    extern __shared__ __align__(16) char dsm[];
    uint32_t* As = (uint32_t*)dsm;                 // 30720 (3*128*20)
    uint32_t* Bs = (uint32_t*)(dsm + 30720);       // 50688 (3*16*264)
    float* sB = (float*)(dsm + 81408);

    const int t0 = blockIdx.x * 128;
    const int c0base = blockIdx.y * 256;
    const int tid = threadIdx.x, w = tid >> 5, l = tid & 31;
    const int wr = w >> 2, wc = w & 3, g = l >> 2, tig = l & 3;

    if (tid < 256) sB[tid] = ob2[c0base + tid];

    float acc[2][8][4];
#pragma unroll
    for (int mt = 0; mt < 2; mt++)
#pragma unroll
        for (int nt = 0; nt < 8; nt++)
#pragma unroll
            for (int i = 0; i < 4; i++) acc[mt][nt][i] = 0.f;

    const int ar = tid >> 2, ac4 = (tid & 3) * 4;
    const float* Ap = g_oact + (size_t)(t0 + ar) * 512 + ac4;

    auto load_stage = [&](int s, int k0) {
        cp16(&As[s * 2560 + ar * 20 + ac4], Ap + k0);
#pragma unroll
        for (int i = 0; i < 2; i++) {
            int idx = tid + 512 * i;
            int kk = idx >> 6, c4 = (idx & 63) * 4;
            cp16(&Bs[s * 4224 + kk * 264 + c4],
                 g_oW2t + (size_t)(k0 + kk) * 512 + c0base + c4);
        }
    };

    load_stage(0, 0);  CP_COMMIT();
    load_stage(1, 16); CP_COMMIT();
    int cur = 0;
    for (int it = 0; it < 32; it++) {
        CP_WAIT_1();
        __syncthreads();
        if (it + 2 < 32) load_stage((cur + 2 >= 3) ? cur - 1 : cur + 2, (it + 2) * 16);
        CP_COMMIT();
        const uint32_t* Ab = &As[cur * 2560];
        const uint32_t* Bb = &Bs[cur * 4224];
#pragma unroll
        for (int ks = 0; ks < 16; ks += 8) {
            uint32_t af[2][4];
#pragma unroll
            for (int mt = 0; mt < 2; mt++) {
                int rb = (wr * 32 + mt * 16 + g) * 20 + ks;
                af[mt][0] = Ab[rb + tig];       af[mt][1] = Ab[rb + 160 + tig];
                af[mt][2] = Ab[rb + tig + 4];   af[mt][3] = Ab[rb + 160 + tig + 4];
            }
#pragma unroll
            for (int nt = 0; nt < 8; nt++) {
                int cb = wc * 64 + nt * 8 + g;
                uint32_t b0 = Bb[(ks + tig) * 264 + cb];
                uint32_t b1 = Bb[(ks + tig + 4) * 264 + cb];
                mma_tf32(acc[0][nt], af[0], b0, b1);
                mma_tf32(acc[1][nt], af[1], b0, b1);
            }
        }
        cur = (cur + 1 == 3) ? 0 : cur + 1;
    }

#pragma unroll
    for (int mt = 0; mt < 2; mt++)
#pragma unroll
        for (int nt = 0; nt < 8; nt++) {
            int c0 = wc * 64 + nt * 8 + 2 * tig;
            int col = c0base + c0;
            int row0 = t0 + wr * 32 + mt * 16 + g;
            size_t o0 = (size_t)row0 * 512 + col;
            size_t o1 = (size_t)(row0 + 8) * 512 + col;
            float2 x0 = *(const float2*)&g_xn[o0];
            float2 x1 = *(const float2*)&g_xn[o1];
            *(float2*)&out[o0] = make_float2(acc[mt][nt][0] + sB[c0] + x0.x,
                                             acc[mt][nt][1] + sB[c0 + 1] + x0.y);
            *(float2*)&out[o1] = make_float2(acc[mt][nt][2] + sB[c0] + x1.x,
                                             acc[mt][nt][3] + sB[c0 + 1] + x1.y);
        }
}

// ============================================================================
extern "C" void kernel_launch(void* const* d_in, const int* in_sizes, int n_in,
                              void* d_out, int out_size)
{
    (void)in_sizes; (void)n_in; (void)out_size;
    const float* x    = (const float*)d_in[0];
    const float* ng   = (const float*)d_in[1];
    const float* nb   = (const float*)d_in[2];
    const float* hW1  = (const float*)d_in[3];
    const float* hb1  = (const float*)d_in[4];
    const float* hlg  = (const float*)d_in[5];
    const float* hlb  = (const float*)d_in[6];
    const float* hW2  = (const float*)d_in[7];
    const float* hb2  = (const float*)d_in[8];
    const float* attr = (const float*)d_in[9];
    const float* dynm = (const float*)d_in[10];
    const float* gW   = (const float*)d_in[11];
    const float* gb   = (const float*)d_in[12];
    const float* oW1  = (const float*)d_in[13];
    const float* ob1  = (const float*)d_in[14];
    const float* olg  = (const float*)d_in[15];
    const float* olb  = (const float*)d_in[16];
    const float* oW2  = (const float*)d_in[17];
    const float* ob2  = (const float*)d_in[18];
    float* out = (float*)d_out;

    cudaFuncSetAttribute(k_head1_mma, cudaFuncAttributeMaxDynamicSharedMemorySize, K2_SMEM);
    cudaFuncSetAttribute(k_head2_mma, cudaFuncAttributeMaxDynamicSharedMemorySize, K3_SMEM);
    cudaFuncSetAttribute(k_out1_mma,  cudaFuncAttributeMaxDynamicSharedMemorySize, K4_SMEM);
    cudaFuncSetAttribute(k_out2_mma,  cudaFuncAttributeMaxDynamicSharedMemorySize, K5_SMEM);

    k_prep<<<4864, 256>>>(hW1, hW2, dynm, oW1, oW2);
    k_ln_gate<<<8192, 128>>>(x, ng, nb, gW, gb);

    dim3 gh(T_TOK / 128, 4);
    k_head1_mma<<<gh, 512, K2_SMEM>>>(hb1, hlg, hlb);
    k_head2_mma<<<gh, 512, K3_SMEM>>>(hb2, attr);

    k_out1_mma<<<T_TOK / 64, 512, K4_SMEM>>>(ob1, olg, olb);
    dim3 g5(T_TOK / 128, 2);
    k_out2_mma<<<g5, 512, K5_SMEM>>>(ob2, out);
}

// round 10
// speedup vs baseline: 1.0676x; 1.0676x over previous
#include <cuda_runtime.h>
#include <math.h>
#include <stdint.h>

// ----------------------------------------------------------------------------
// NoiseRobustAttractorLayer — TF32 mma.sync. R10: R8 structure (best verified),
// K2/K4/K5 upgraded to 4-stage cp.async rings (prefetch-3, wait_group 2),
// K1 rewritten warp-per-token (no block barriers). K3 = R8 verbatim.
// ----------------------------------------------------------------------------

#define T_TOK 65536
#define EPSV  1e-5f

__device__ float g_xn  [(size_t)T_TOK * 512];   // fp32 (residual)
__device__ float g_xnt [(size_t)T_TOK * 512];   // tf32-rounded (GEMM A)
__device__ float g_gate[(size_t)T_TOK * 4];
__device__ float g_h   [(size_t)T_TOK * 1024];  // tf32-rounded
__device__ float g_comb[(size_t)T_TOK * 512];   // tf32-rounded
__device__ float g_oact[(size_t)T_TOK * 512];   // tf32-rounded

__device__ float g_hW1t[4 * 512 * 256];
__device__ float g_hW2t[4 * 256 * 128];
__device__ float g_dynt[4 * 128 * 128];
__device__ float g_oW1t[512 * 512];
__device__ float g_oW2t[512 * 512];

__device__ __forceinline__ float warp_sum(float v) {
#pragma unroll
    for (int o = 16; o > 0; o >>= 1) v += __shfl_xor_sync(0xffffffffu, v, o);
    return v;
}
__device__ __forceinline__ float gelu_exact(float x) {
    return 0.5f * x * (1.0f + erff(x * 0.70710678118654752f));
}
__device__ __forceinline__ uint32_t f2tf(float x) {
    uint32_t r; asm("cvt.rna.tf32.f32 %0, %1;" : "=r"(r) : "f"(x)); return r;
}
__device__ __forceinline__ float f2tf_f(float x) {
    return __uint_as_float(f2tf(x));
}
__device__ __forceinline__ void mma_tf32(float c[4], const uint32_t a[4],
                                         uint32_t b0, uint32_t b1) {
    asm volatile(
        "mma.sync.aligned.m16n8k8.row.col.f32.tf32.tf32.f32 "
        "{%0,%1,%2,%3},{%4,%5,%6,%7},{%8,%9},{%0,%1,%2,%3};"
        : "+f"(c[0]), "+f"(c[1]), "+f"(c[2]), "+f"(c[3])
        : "r"(a[0]), "r"(a[1]), "r"(a[2]), "r"(a[3]), "r"(b0), "r"(b1));
}
__device__ __forceinline__ void cp16(void* s, const void* g) {
    uint32_t sa = (uint32_t)__cvta_generic_to_shared(s);
    asm volatile("cp.async.cg.shared.global [%0], [%1], 16;" :: "r"(sa), "l"(g));
}
#define CP_COMMIT()  asm volatile("cp.async.commit_group;")
#define CP_WAIT_1()  asm volatile("cp.async.wait_group 1;" ::: "memory")
#define CP_WAIT_2()  asm volatile("cp.async.wait_group 2;" ::: "memory")

// ============================================================================
// K0: weight pre-conversion fp32 -> tf32
// ============================================================================
__global__ void __launch_bounds__(256) k_prep(
    const float* __restrict__ hW1, const float* __restrict__ hW2,
    const float* __restrict__ dynm, const float* __restrict__ oW1,
    const float* __restrict__ oW2)
{
    int i = blockIdx.x * 256 + threadIdx.x;
    if (i < 524288)       g_hW1t[i]           = f2tf_f(hW1[i]);
    else if (i < 655360)  g_hW2t[i - 524288]  = f2tf_f(hW2[i - 524288]);
    else if (i < 720896)  g_dynt[i - 655360]  = f2tf_f(dynm[i - 655360]);
    else if (i < 983040)  g_oW1t[i - 720896]  = f2tf_f(oW1[i - 720896]);
    else if (i < 1245184) g_oW2t[i - 983040]  = f2tf_f(oW2[i - 983040]);
}

// ============================================================================
// K1: warp-per-token LN + gate. block 256 (8 warps), grid 8192 -> 1 token/warp.
// No block barriers in the token loop — warp shuffles only.
// ============================================================================
__global__ void __launch_bounds__(256) k_ln_gate(
    const float* __restrict__ x, const float* __restrict__ ng,
    const float* __restrict__ nb, const float* __restrict__ gW,
    const float* __restrict__ gb)
{
    __shared__ float sgW[2048];
    __shared__ float sng[512], snb[512];
    const int tid = threadIdx.x;
    for (int i = tid; i < 2048; i += 256) sgW[i] = gW[i];
    for (int i = tid; i < 512; i += 256) { sng[i] = ng[i]; snb[i] = nb[i]; }
    __syncthreads();

    const int wid = tid >> 5, l = tid & 31;
    const float gb0 = gb[0], gb1 = gb[1], gb2 = gb[2], gb3 = gb[3];
    const float4* sgW4 = (const float4*)sgW;
    const float4* sng4 = (const float4*)sng;
    const float4* snb4 = (const float4*)snb;

    for (int t = blockIdx.x * 8 + wid; t < T_TOK; t += gridDim.x * 8) {
        const float4* xr = (const float4*)(x + (size_t)t * 512);
        float4 v[4];
#pragma unroll
        for (int j = 0; j < 4; j++) v[j] = xr[l + 32 * j];
        float s = 0.f;
#pragma unroll
        for (int j = 0; j < 4; j++) s += v[j].x + v[j].y + v[j].z + v[j].w;
        s = warp_sum(s);
        float m = s * (1.0f / 512.0f);
        float q = 0.f;
#pragma unroll
        for (int j = 0; j < 4; j++) {
            float dx = v[j].x - m, dy = v[j].y - m, dz = v[j].z - m, dw = v[j].w - m;
            q += dx * dx + dy * dy + dz * dz + dw * dw;
        }
        q = warp_sum(q);
        float rs = rsqrtf(q * (1.0f / 512.0f) + EPSV);

        float4 xnv[4];
        float4* xo  = (float4*)(g_xn  + (size_t)t * 512);
        float4* xot = (float4*)(g_xnt + (size_t)t * 512);
#pragma unroll
        for (int j = 0; j < 4; j++) {
            float4 gv = sng4[l + 32 * j];
            float4 bv = snb4[l + 32 * j];
            xnv[j].x = (v[j].x - m) * rs * gv.x + bv.x;
            xnv[j].y = (v[j].y - m) * rs * gv.y + bv.y;
            xnv[j].z = (v[j].z - m) * rs * gv.z + bv.z;
            xnv[j].w = (v[j].w - m) * rs * gv.w + bv.w;
            xo[l + 32 * j] = xnv[j];
            float4 tv;
            tv.x = f2tf_f(xnv[j].x); tv.y = f2tf_f(xnv[j].y);
            tv.z = f2tf_f(xnv[j].z); tv.w = f2tf_f(xnv[j].w);
            xot[l + 32 * j] = tv;
        }
        float p[4] = {0.f, 0.f, 0.f, 0.f};
#pragma unroll
        for (int h = 0; h < 4; h++) {
#pragma unroll
            for (int j = 0; j < 4; j++) {
                float4 wv = sgW4[h * 128 + l + 32 * j];
                p[h] += xnv[j].x * wv.x + xnv[j].y * wv.y
                      + xnv[j].z * wv.z + xnv[j].w * wv.w;
            }
            p[h] = warp_sum(p[h]);
        }
        if (l == 0) {
            g_gate[(size_t)t * 4 + 0] = 1.0f / (1.0f + expf(-(p[0] + gb0)));
            g_gate[(size_t)t * 4 + 1] = 1.0f / (1.0f + expf(-(p[1] + gb1)));
            g_gate[(size_t)t * 4 + 2] = 1.0f / (1.0f + expf(-(p[2] + gb2)));
            g_gate[(size_t)t * 4 + 3] = 1.0f / (1.0f + expf(-(p[3] + gb3)));
        }
    }
}

// ============================================================================
// K2: h = gelu(LN(xn @ hW1[h] + hb1)).  BM=64,BN=256, block 256, 4-stage ring.
// smem: As 20480 | Bs 67584 | sB sG sBt 3072 | ps pq 2048 = 93184 B (2 CTAs)
// ============================================================================
#define K2_SMEM 93184
__global__ void __launch_bounds__(256) k_head1_mma(
    const float* __restrict__ hb1,
    const float* __restrict__ hlg, const float* __restrict__ hlb)
{
    extern __shared__ __align__(16) char dsm[];
    uint32_t* As = (uint32_t*)dsm;                 // 20480 (4*64*20)
    uint32_t* Bs = (uint32_t*)(dsm + 20480);       // 67584 (4*16*264)
    float* sB  = (float*)(dsm + 88064);
    float* sG  = (float*)(dsm + 89088);
    float* sBt = (float*)(dsm + 90112);
    float* ps  = (float*)(dsm + 91136);            // 64*4
    float* pq  = (float*)(dsm + 92160);            // 64*4

    const int h = blockIdx.y;
    const int t0 = blockIdx.x * 64;
    const int tid = threadIdx.x, w = tid >> 5, l = tid & 31;
    const int wr = w >> 2, wc = w & 3, g = l >> 2, tig = l & 3;

    sB[tid] = hb1[h * 256 + tid]; sG[tid] = hlg[h * 256 + tid]; sBt[tid] = hlb[h * 256 + tid];

    float acc[2][8][4];
#pragma unroll
    for (int mt = 0; mt < 2; mt++)
#pragma unroll
        for (int nt = 0; nt < 8; nt++)
#pragma unroll
            for (int i = 0; i < 4; i++) acc[mt][nt][i] = 0.f;

    const float* Wp = g_hW1t + (size_t)h * 512 * 256;
    const int ar = tid >> 2, ac4 = (tid & 3) * 4;
    const float* Ap = g_xnt + (size_t)(t0 + ar) * 512 + ac4;

    auto load_stage = [&](int s, int k0) {
        cp16(&As[s * 1280 + ar * 20 + ac4], Ap + k0);
#pragma unroll
        for (int i = 0; i < 4; i++) {
            int idx = tid + 256 * i;
            int kk = idx >> 6, c4 = (idx & 63) * 4;
            cp16(&Bs[s * 4224 + kk * 264 + c4], Wp + (size_t)(k0 + kk) * 256 + c4);
        }
    };

    load_stage(0, 0);  CP_COMMIT();
    load_stage(1, 16); CP_COMMIT();
    load_stage(2, 32); CP_COMMIT();
    int cur = 0;
    for (int it = 0; it < 32; it++) {
        CP_WAIT_2();
        __syncthreads();
        if (it + 3 < 32) load_stage((cur + 3) & 3, (it + 3) * 16);
        CP_COMMIT();
        const uint32_t* Ab = &As[cur * 1280];
        const uint32_t* Bb = &Bs[cur * 4224];
#pragma unroll
        for (int ks = 0; ks < 16; ks += 8) {
            uint32_t af[2][4];
#pragma unroll
            for (int mt = 0; mt < 2; mt++) {
                int rb = (wr * 32 + mt * 16 + g) * 20 + ks;
                af[mt][0] = Ab[rb + tig];       af[mt][1] = Ab[rb + 160 + tig];
                af[mt][2] = Ab[rb + tig + 4];   af[mt][3] = Ab[rb + 160 + tig + 4];
            }
#pragma unroll
            for (int nt = 0; nt < 8; nt++) {
                int cb = wc * 64 + nt * 8 + g;
                uint32_t b0 = Bb[(ks + tig) * 264 + cb];
                uint32_t b1 = Bb[(ks + tig + 4) * 264 + cb];
                mma_tf32(acc[0][nt], af[0], b0, b1);
                mma_tf32(acc[1][nt], af[1], b0, b1);
            }
        }
        cur = (cur + 1) & 3;
    }
    __syncthreads();

    // epilogue: bias + LN(256) + gelu ; store tf32-rounded
    float rsm[4] = {0, 0, 0, 0}, rsq[4] = {0, 0, 0, 0};
#pragma unroll
    for (int mt = 0; mt < 2; mt++)
#pragma unroll
        for (int nt = 0; nt < 8; nt++) {
            int c0 = wc * 64 + nt * 8 + 2 * tig;
            float v0 = acc[mt][nt][0] + sB[c0], v1 = acc[mt][nt][1] + sB[c0 + 1];
            float v2 = acc[mt][nt][2] + sB[c0], v3 = acc[mt][nt][3] + sB[c0 + 1];
            acc[mt][nt][0] = v0; acc[mt][nt][1] = v1; acc[mt][nt][2] = v2; acc[mt][nt][3] = v3;
            rsm[mt * 2 + 0] += v0 + v1; rsq[mt * 2 + 0] += v0 * v0 + v1 * v1;
            rsm[mt * 2 + 1] += v2 + v3; rsq[mt * 2 + 1] += v2 * v2 + v3 * v3;
        }
#pragma unroll
    for (int off = 1; off < 4; off <<= 1)
#pragma unroll
        for (int q = 0; q < 4; q++) {
            rsm[q] += __shfl_xor_sync(0xffffffffu, rsm[q], off);
            rsq[q] += __shfl_xor_sync(0xffffffffu, rsq[q], off);
        }
    if (tig == 0) {
#pragma unroll
        for (int q = 0; q < 4; q++) {
            int row = wr * 32 + (q >> 1) * 16 + (q & 1) * 8 + g;
            ps[row * 4 + wc] = rsm[q]; pq[row * 4 + wc] = rsq[q];
        }
    }
    __syncthreads();
    float mv[4], rv[4];
#pragma unroll
    for (int q = 0; q < 4; q++) {
        int row = wr * 32 + (q >> 1) * 16 + (q & 1) * 8 + g;
        float s  = ps[row * 4 + 0] + ps[row * 4 + 1] + ps[row * 4 + 2] + ps[row * 4 + 3];
        float s2 = pq[row * 4 + 0] + pq[row * 4 + 1] + pq[row * 4 + 2] + pq[row * 4 + 3];
        float m = s * (1.f / 256.f);
        float var = s2 * (1.f / 256.f) - m * m;
        mv[q] = m; rv[q] = rsqrtf(var + EPSV);
    }
#pragma unroll
    for (int mt = 0; mt < 2; mt++)
#pragma unroll
        for (int nt = 0; nt < 8; nt++) {
            int c0 = wc * 64 + nt * 8 + 2 * tig;
            int q0 = mt * 2;
            int row0 = t0 + wr * 32 + mt * 16 + g;
            float u0 = gelu_exact((acc[mt][nt][0] - mv[q0]) * rv[q0] * sG[c0] + sBt[c0]);
            float u1 = gelu_exact((acc[mt][nt][1] - mv[q0]) * rv[q0] * sG[c0 + 1] + sBt[c0 + 1]);
            *(float2*)&g_h[(size_t)row0 * 1024 + h * 256 + c0] =
                make_float2(f2tf_f(u0), f2tf_f(u1));
            float u2 = gelu_exact((acc[mt][nt][2] - mv[q0 + 1]) * rv[q0 + 1] * sG[c0] + sBt[c0]);
            float u3 = gelu_exact((acc[mt][nt][3] - mv[q0 + 1]) * rv[q0 + 1] * sG[c0 + 1] + sBt[c0 + 1]);
            *(float2*)&g_h[(size_t)(row0 + 8) * 1024 + h * 256 + c0] =
                make_float2(f2tf_f(u2), f2tf_f(u3));
        }
}

// ============================================================================
// K3: state GEMM (3-stage) ; [dyn|sa] GEMM (3-stage) ; softmax mix.
// (R8 verbatim — 256 threads, 2 CTAs/SM.)
// ============================================================================
#define K3_SMEM 88864
__global__ void __launch_bounds__(256, 2) k_head2_mma(
    const float* __restrict__ hb2, const float* __restrict__ attr)
{
    extern __shared__ __align__(16) char dsm[];
    uint32_t* As  = (uint32_t*)dsm;                // 15360 (3*64*20)
    uint32_t* Bs  = (uint32_t*)(dsm + 15360);      // 26112 (3*16*136)
    float*    Ss  = (float*)(dsm + 41472);         // 33792 (64*132)
    float*    At  = (float*)(dsm + 75264);         //  4096 (8*128)
    uint32_t* AtT = (uint32_t*)(dsm + 79360);      //  4096 (128*8)
    float*    Sa  = (float*)(dsm + 83456);         //  2048
    float*    Sw  = (float*)(dsm + 85504);         //  2048
    float*    s2p = (float*)(dsm + 87552);         //  1024
    float*    a2s = (float*)(dsm + 88576);         //    32
    float*    Sgt = (float*)(dsm + 88608);         //   256

    const int h = blockIdx.y;
    const int t0 = blockIdx.x * 64;
    const int tid = threadIdx.x, w = tid >> 5, l = tid & 31;
    const int wr = w >> 2, wc = w & 3, g = l >> 2, tig = l & 3;

    {
        float4 v = *(const float4*)(attr + (size_t)h * 1024 + tid * 4);
        *(float4*)&At[tid * 4] = v;
        int a0 = tid >> 5, d0 = (tid & 31) * 4;
        AtT[(d0 + 0) * 8 + a0] = f2tf(v.x);
        AtT[(d0 + 1) * 8 + a0] = f2tf(v.y);
        AtT[(d0 + 2) * 8 + a0] = f2tf(v.z);
        AtT[(d0 + 3) * 8 + a0] = f2tf(v.w);
    }

    float acc[2][4][4];
#pragma unroll
    for (int mt = 0; mt < 2; mt++)
#pragma unroll
        for (int nt = 0; nt < 4; nt++)
#pragma unroll
            for (int i = 0; i < 4; i++) acc[mt][nt][i] = 0.f;

    const int ar = tid >> 2, ac4 = (tid & 3) * 4;
    const float* Ap = g_h + (size_t)(t0 + ar) * 1024 + h * 256 + ac4;
    const float* Wp = g_hW2t + (size_t)h * 256 * 128;

    auto load_stage1 = [&](int s, int k0) {
        cp16(&As[s * 1280 + ar * 20 + ac4], Ap + k0);
#pragma unroll
        for (int i = 0; i < 2; i++) {
            int idx = tid + 256 * i;
            int kk = idx >> 5, c4 = (idx & 31) * 4;
            cp16(&Bs[s * 2176 + kk * 136 + c4], Wp + (size_t)(k0 + kk) * 128 + c4);
        }
    };

    load_stage1(0, 0);  CP_COMMIT();
    load_stage1(1, 16); CP_COMMIT();
    __syncthreads();
    if (tid < 8) {
        float q = 0.f;
#pragma unroll
        for (int k = 0; k < 128; k++) q += At[tid * 128 + k] * At[tid * 128 + k];
        a2s[tid] = q;
    }

    int cur = 0;
    for (int it = 0; it < 16; it++) {
        CP_WAIT_1();
        __syncthreads();
        if (it + 2 < 16) load_stage1((cur + 2 >= 3) ? cur - 1 : cur + 2, (it + 2) * 16);
        CP_COMMIT();
        const uint32_t* Ab = &As[cur * 1280];
        const uint32_t* Bb = &Bs[cur * 2176];
#pragma unroll
        for (int ks = 0; ks < 16; ks += 8) {
            uint32_t af[2][4];
#pragma unroll
            for (int mt = 0; mt < 2; mt++) {
                int rb = (wr * 32 + mt * 16 + g) * 20 + ks;
                af[mt][0] = Ab[rb + tig];       af[mt][1] = Ab[rb + 160 + tig];
                af[mt][2] = Ab[rb + tig + 4];   af[mt][3] = Ab[rb + 160 + tig + 4];
            }
#pragma unroll
            for (int nt = 0; nt < 4; nt++) {
                int cb = wc * 32 + nt * 8 + g;
                uint32_t b0 = Bb[(ks + tig) * 136 + cb];
                uint32_t b1 = Bb[(ks + tig + 4) * 136 + cb];
                mma_tf32(acc[0][nt], af[0], b0, b1);
                mma_tf32(acc[1][nt], af[1], b0, b1);
            }
        }
        cur = (cur + 1 == 3) ? 0 : cur + 1;
    }
    __syncthreads();

    const float* Dp = g_dynt + (size_t)h * 128 * 128;
    auto load_stage2 = [&](int s, int k0) {
#pragma unroll
        for (int i = 0; i < 2; i++) {
            int idx = tid + 256 * i;
            int kk = idx >> 5, c4 = (idx & 31) * 4;
            cp16(&Bs[s * 2176 + kk * 136 + c4], Dp + (size_t)(k0 + kk) * 128 + c4);
        }
    };
    load_stage2(0, 0);  CP_COMMIT();
    load_stage2(1, 16); CP_COMMIT();

    {
        float rq[4] = {0, 0, 0, 0};
#pragma unroll
        for (int mt = 0; mt < 2; mt++)
#pragma unroll
            for (int nt = 0; nt < 4; nt++) {
                int c0 = wc * 32 + nt * 8 + 2 * tig;
                int row = wr * 32 + mt * 16 + g;
                float b0v = hb2[h * 128 + c0], b1v = hb2[h * 128 + c0 + 1];
                float v0 = f2tf_f(acc[mt][nt][0] + b0v);
                float v1 = f2tf_f(acc[mt][nt][1] + b1v);
                float v2 = f2tf_f(acc[mt][nt][2] + b0v);
                float v3 = f2tf_f(acc[mt][nt][3] + b1v);
                Ss[row * 132 + c0]           = v0;
                Ss[row * 132 + c0 + 1]       = v1;
                Ss[(row + 8) * 132 + c0]     = v2;
                Ss[(row + 8) * 132 + c0 + 1] = v3;
                rq[mt * 2 + 0] += v0 * v0 + v1 * v1;
                rq[mt * 2 + 1] += v2 * v2 + v3 * v3;
            }
#pragma unroll
        for (int off = 1; off < 4; off <<= 1)
#pragma unroll
            for (int q = 0; q < 4; q++)
                rq[q] += __shfl_xor_sync(0xffffffffu, rq[q], off);
        if (tig == 0) {
#pragma unroll
            for (int q = 0; q < 4; q++) {
                int row = wr * 32 + (q >> 1) * 16 + (q & 1) * 8 + g;
                s2p[row * 4 + wc] = rq[q];
            }
        }
    }
    __syncthreads();

    float dcc[2][4][4];
    float scc[2][4];
#pragma unroll
    for (int mt = 0; mt < 2; mt++) {
#pragma unroll
        for (int nt = 0; nt < 4; nt++)
#pragma unroll
            for (int i = 0; i < 4; i++) dcc[mt][nt][i] = 0.f;
#pragma unroll
        for (int i = 0; i < 4; i++) scc[mt][i] = 0.f;
    }

    cur = 0;
    for (int it = 0; it < 8; it++) {
        CP_WAIT_1();
        __syncthreads();
        if (it + 2 < 8) load_stage2((cur + 2 >= 3) ? cur - 1 : cur + 2, (it + 2) * 16);
        CP_COMMIT();
        const uint32_t* Bb = &Bs[cur * 2176];
        const int kbase = it * 16;
#pragma unroll
        for (int ks = 0; ks < 16; ks += 8) {
            uint32_t af[2][4];
#pragma unroll
            for (int mt = 0; mt < 2; mt++) {
                int rb = (wr * 32 + mt * 16 + g) * 132 + kbase + ks;
                af[mt][0] = __float_as_uint(Ss[rb + tig]);
                af[mt][1] = __float_as_uint(Ss[rb + 8 * 132 + tig]);
                af[mt][2] = __float_as_uint(Ss[rb + tig + 4]);
                af[mt][3] = __float_as_uint(Ss[rb + 8 * 132 + tig + 4]);
            }
#pragma unroll
            for (int nt = 0; nt < 4; nt++) {
                int cb = wc * 32 + nt * 8 + g;
                uint32_t b0 = Bb[(ks + tig) * 136 + cb];
                uint32_t b1 = Bb[(ks + tig + 4) * 136 + cb];
                mma_tf32(dcc[0][nt], af[0], b0, b1);
                mma_tf32(dcc[1][nt], af[1], b0, b1);
            }
            uint32_t b0s = AtT[(kbase + ks + tig) * 8 + g];
            uint32_t b1s = AtT[(kbase + ks + tig + 4) * 8 + g];
            mma_tf32(scc[0], af[0], b0s, b1s);
            mma_tf32(scc[1], af[1], b0s, b1s);
        }
        cur = (cur + 1 == 3) ? 0 : cur + 1;
    }
    __syncthreads();

    if (wc == 0) {
#pragma unroll
        for (int mt = 0; mt < 2; mt++) {
            int row = wr * 32 + mt * 16 + g;
            Sa[row * 8 + 2 * tig]           = scc[mt][0];
            Sa[row * 8 + 2 * tig + 1]       = scc[mt][1];
            Sa[(row + 8) * 8 + 2 * tig]     = scc[mt][2];
            Sa[(row + 8) * 8 + 2 * tig + 1] = scc[mt][3];
        }
    }
    __syncthreads();

    const float invs = 0.08838834764831845f;  // 1/sqrt(128)
    if (tid < 64) {
        int row = tid;
        float s2 = s2p[row * 4 + 0] + s2p[row * 4 + 1] + s2p[row * 4 + 2] + s2p[row * 4 + 3];
        float lgt[8], mx = -1e30f;
#pragma unroll
        for (int a = 0; a < 8; a++) {
            float dd = sqrtf(fmaxf(s2 + a2s[a] - 2.0f * Sa[row * 8 + a], 0.0f));
            lgt[a] = -dd * invs;
            mx = fmaxf(mx, lgt[a]);
        }
        float e[8], se = 0.f;
#pragma unroll
        for (int a = 0; a < 8; a++) { e[a] = expf(lgt[a] - mx); se += e[a]; }
        float ise = 1.0f / se;
#pragma unroll
        for (int a = 0; a < 8; a++) Sw[row * 8 + a] = e[a] * ise;
        Sgt[row] = 0.1f * g_gate[(size_t)(t0 + row) * 4 + h];
    }
    __syncthreads();

#pragma unroll
    for (int mt = 0; mt < 2; mt++)
#pragma unroll
        for (int nt = 0; nt < 4; nt++) {
            int c0 = wc * 32 + nt * 8 + 2 * tig;
#pragma unroll
            for (int half = 0; half < 2; half++) {
                int row = wr * 32 + mt * 16 + g + 8 * half;
                float gt = Sgt[row];
                float sv0 = Ss[row * 132 + c0];
                float sv1 = Ss[row * 132 + c0 + 1];
                float ai0 = 0.f, ai1 = 0.f;
#pragma unroll
                for (int a = 0; a < 8; a++) {
                    float wgt = Sw[row * 8 + a];
                    ai0 += wgt * At[a * 128 + c0];
                    ai1 += wgt * At[a * 128 + c0 + 1];
                }
                float dv0 = dcc[mt][nt][2 * half + 0];
                float dv1 = dcc[mt][nt][2 * half + 1];
                float o0 = f2tf_f(sv0 + gt * (ai0 - sv0 + tanhf(dv0)));
                float o1 = f2tf_f(sv1 + gt * (ai1 - sv1 + tanhf(dv1)));
                *(float2*)&g_comb[(size_t)(t0 + row) * 512 + h * 128 + c0] =
                    make_float2(o0, o1);
            }
        }
}

// ============================================================================
// K4: o1 = gelu(LN(comb @ oW1 + ob1)).  BM=64,BN=512, block 512, 4-stage ring.
// smem: As 20480 | Bs 133120 | sB sG sBt 6144 | ps pq 4096 = 163840 B
// ============================================================================
#define K4_SMEM 163840
__global__ void __launch_bounds__(512) k_out1_mma(
    const float* __restrict__ ob1,
    const float* __restrict__ olg, const float* __restrict__ olb)
{
    extern __shared__ __align__(16) char dsm[];
    uint32_t* As = (uint32_t*)dsm;                 // 20480 (4*64*20)
    uint32_t* Bs = (uint32_t*)(dsm + 20480);       // 133120 (4*16*520)
    float* sB  = (float*)(dsm + 153600);
    float* sG  = (float*)(dsm + 155648);
    float* sBt = (float*)(dsm + 157696);
    float* ps  = (float*)(dsm + 159744);           // 64*8
    float* pq  = (float*)(dsm + 161792);

    const int t0 = blockIdx.x * 64;
    const int tid = threadIdx.x, w = tid >> 5, l = tid & 31;
    const int wr = w >> 3, wc = w & 7, g = l >> 2, tig = l & 3;

    sB[tid] = ob1[tid]; sG[tid] = olg[tid]; sBt[tid] = olb[tid];

    float acc[2][8][4];
#pragma unroll
    for (int mt = 0; mt < 2; mt++)
#pragma unroll
        for (int nt = 0; nt < 8; nt++)
#pragma unroll
            for (int i = 0; i < 4; i++) acc[mt][nt][i] = 0.f;

    const int ar = tid >> 2, ac4 = (tid & 3) * 4;
    const float* Ap = g_comb + (size_t)(t0 + (ar & 63)) * 512 + ac4;

    auto load_stage = [&](int s, int k0) {
        if (tid < 256) cp16(&As[s * 1280 + ar * 20 + ac4], Ap + k0);
#pragma unroll
        for (int i = 0; i < 4; i++) {
            int idx = tid + 512 * i;
            int kk = idx >> 7, c4 = (idx & 127) * 4;
            cp16(&Bs[s * 8320 + kk * 520 + c4], g_oW1t + (size_t)(k0 + kk) * 512 + c4);
        }
    };

    load_stage(0, 0);  CP_COMMIT();
    load_stage(1, 16); CP_COMMIT();
    load_stage(2, 32); CP_COMMIT();
    int cur = 0;
    for (int it = 0; it < 32; it++) {
        CP_WAIT_2();
        __syncthreads();
        if (it + 3 < 32) load_stage((cur + 3) & 3, (it + 3) * 16);
        CP_COMMIT();
        const uint32_t* Ab = &As[cur * 1280];
        const uint32_t* Bb = &Bs[cur * 8320];
#pragma unroll
        for (int ks = 0; ks < 16; ks += 8) {
            uint32_t af[2][4];
#pragma unroll
            for (int mt = 0; mt < 2; mt++) {
                int rb = (wr * 32 + mt * 16 + g) * 20 + ks;
                af[mt][0] = Ab[rb + tig];       af[mt][1] = Ab[rb + 160 + tig];
                af[mt][2] = Ab[rb + tig + 4];   af[mt][3] = Ab[rb + 160 + tig + 4];
            }
#pragma unroll
            for (int nt = 0; nt < 8; nt++) {
                int cb = wc * 64 + nt * 8 + g;
                uint32_t b0 = Bb[(ks + tig) * 520 + cb];
                uint32_t b1 = Bb[(ks + tig + 4) * 520 + cb];
                mma_tf32(acc[0][nt], af[0], b0, b1);
                mma_tf32(acc[1][nt], af[1], b0, b1);
            }
        }
        cur = (cur + 1) & 3;
    }
    __syncthreads();

    float rsm[4] = {0, 0, 0, 0}, rsq[4] = {0, 0, 0, 0};
#pragma unroll
    for (int mt = 0; mt < 2; mt++)
#pragma unroll
        for (int nt = 0; nt < 8; nt++) {
            int c0 = wc * 64 + nt * 8 + 2 * tig;
            float v0 = acc[mt][nt][0] + sB[c0], v1 = acc[mt][nt][1] + sB[c0 + 1];
            float v2 = acc[mt][nt][2] + sB[c0], v3 = acc[mt][nt][3] + sB[c0 + 1];
            acc[mt][nt][0] = v0; acc[mt][nt][1] = v1; acc[mt][nt][2] = v2; acc[mt][nt][3] = v3;
            rsm[mt * 2 + 0] += v0 + v1; rsq[mt * 2 + 0] += v0 * v0 + v1 * v1;
            rsm[mt * 2 + 1] += v2 + v3; rsq[mt * 2 + 1] += v2 * v2 + v3 * v3;
        }
#pragma unroll
    for (int off = 1; off < 4; off <<= 1)
#pragma unroll
        for (int q = 0; q < 4; q++) {
            rsm[q] += __shfl_xor_sync(0xffffffffu, rsm[q], off);
            rsq[q] += __shfl_xor_sync(0xffffffffu, rsq[q], off);
        }
    if (tig == 0) {
#pragma unroll
        for (int q = 0; q < 4; q++) {
            int row = wr * 32 + (q >> 1) * 16 + (q & 1) * 8 + g;
            ps[row * 8 + wc] = rsm[q]; pq[row * 8 + wc] = rsq[q];
        }
    }
    __syncthreads();
    float mv[4], rv[4];
#pragma unroll
    for (int q = 0; q < 4; q++) {
        int row = wr * 32 + (q >> 1) * 16 + (q & 1) * 8 + g;
        float s = 0.f, s2 = 0.f;
#pragma unroll
        for (int j = 0; j < 8; j++) { s += ps[row * 8 + j]; s2 += pq[row * 8 + j]; }
        float m = s * (1.f / 512.f);
        float var = s2 * (1.f / 512.f) - m * m;
        mv[q] = m; rv[q] = rsqrtf(var + EPSV);
    }
#pragma unroll
    for (int mt = 0; mt < 2; mt++)
#pragma unroll
        for (int nt = 0; nt < 8; nt++) {
            int c0 = wc * 64 + nt * 8 + 2 * tig;
            int q0 = mt * 2;
            int row0 = t0 + wr * 32 + mt * 16 + g;
            float u0 = gelu_exact((acc[mt][nt][0] - mv[q0]) * rv[q0] * sG[c0] + sBt[c0]);
            float u1 = gelu_exact((acc[mt][nt][1] - mv[q0]) * rv[q0] * sG[c0 + 1] + sBt[c0 + 1]);
            *(float2*)&g_oact[(size_t)row0 * 512 + c0] = make_float2(f2tf_f(u0), f2tf_f(u1));
            float u2 = gelu_exact((acc[mt][nt][2] - mv[q0 + 1]) * rv[q0 + 1] * sG[c0] + sBt[c0]);
            float u3 = gelu_exact((acc[mt][nt][3] - mv[q0 + 1]) * rv[q0 + 1] * sG[c0 + 1] + sBt[c0 + 1]);
            *(float2*)&g_oact[(size_t)(row0 + 8) * 512 + c0] = make_float2(f2tf_f(u2), f2tf_f(u3));
        }
}

// ============================================================================
// K5: out = xn + oact @ oW2 + ob2.  BM=64,BN=512, block 512, 4-stage ring.
// smem: As 20480 | Bs 133120 | sB 2048 = 155648 B
// ============================================================================
#define K5_SMEM 155648
__global__ void __launch_bounds__(512) k_out2_mma(
    const float* __restrict__ ob2, float* __restrict__ out)
{
    extern __shared__ __align__(16) char dsm[];
    uint32_t* As = (uint32_t*)dsm;                 // 20480
    uint32_t* Bs = (uint32_t*)(dsm + 20480);       // 133120
    float* sB = (float*)(dsm + 153600);

    const int t0 = blockIdx.x * 64;
    const int tid = threadIdx.x, w = tid >> 5, l = tid & 31;
    const int wr = w >> 3, wc = w & 7, g = l >> 2, tig = l & 3;

    sB[tid] = ob2[tid];

    float acc[2][8][4];
#pragma unroll
    for (int mt = 0; mt < 2; mt++)
#pragma unroll
        for (int nt = 0; nt < 8; nt++)
#pragma unroll
            for (int i = 0; i < 4; i++) acc[mt][nt][i] = 0.f;

    const int ar = tid >> 2, ac4 = (tid & 3) * 4;
    const float* Ap = g_oact + (size_t)(t0 + (ar & 63)) * 512 + ac4;

    auto load_stage = [&](int s, int k0) {
        if (tid < 256) cp16(&As[s * 1280 + ar * 20 + ac4], Ap + k0);
#pragma unroll
        for (int i = 0; i < 4; i++) {
            int idx = tid + 512 * i;
            int kk = idx >> 7, c4 = (idx & 127) * 4;
            cp16(&Bs[s * 8320 + kk * 520 + c4], g_oW2t + (size_t)(k0 + kk) * 512 + c4);
        }
    };

    load_stage(0, 0);  CP_COMMIT();
    load_stage(1, 16); CP_COMMIT();
    load_stage(2, 32); CP_COMMIT();
    int cur = 0;
    for (int it = 0; it < 32; it++) {
        CP_WAIT_2();
        __syncthreads();
        if (it + 3 < 32) load_stage((cur + 3) & 3, (it + 3) * 16);
        CP_COMMIT();
        const uint32_t* Ab = &As[cur * 1280];
        const uint32_t* Bb = &Bs[cur * 8320];
#pragma unroll
        for (int ks = 0; ks < 16; ks += 8) {
            uint32_t af[2][4];
#pragma unroll
            for (int mt = 0; mt < 2; mt++) {
                int rb = (wr * 32 + mt * 16 + g) * 20 + ks;
                af[mt][0] = Ab[rb + tig];       af[mt][1] = Ab[rb + 160 + tig];
                af[mt][2] = Ab[rb + tig + 4];   af[mt][3] = Ab[rb + 160 + tig + 4];
            }
#pragma unroll
            for (int nt = 0; nt < 8; nt++) {
                int cb = wc * 64 + nt * 8 + g;
                uint32_t b0 = Bb[(ks + tig) * 520 + cb];
                uint32_t b1 = Bb[(ks + tig + 4) * 520 + cb];
                mma_tf32(acc[0][nt], af[0], b0, b1);
                mma_tf32(acc[1][nt], af[1], b0, b1);
            }
        }
        cur = (cur + 1) & 3;
    }

#pragma unroll
    for (int mt = 0; mt < 2; mt++)
#pragma unroll
        for (int nt = 0; nt < 8; nt++) {
            int c0 = wc * 64 + nt * 8 + 2 * tig;
            int row0 = t0 + wr * 32 + mt * 16 + g;
            size_t o0 = (size_t)row0 * 512 + c0;
            size_t o1 = (size_t)(row0 + 8) * 512 + c0;
            float2 x0 = *(const float2*)&g_xn[o0];
            float2 x1 = *(const float2*)&g_xn[o1];
            *(float2*)&out[o0] = make_float2(acc[mt][nt][0] + sB[c0] + x0.x,
                                             acc[mt][nt][1] + sB[c0 + 1] + x0.y);
            *(float2*)&out[o1] = make_float2(acc[mt][nt][2] + sB[c0] + x1.x,
                                             acc[mt][nt][3] + sB[c0 + 1] + x1.y);
        }
}

// ============================================================================
extern "C" void kernel_launch(void* const* d_in, const int* in_sizes, int n_in,
                              void* d_out, int out_size)
{
    (void)in_sizes; (void)n_in; (void)out_size;
    const float* x    = (const float*)d_in[0];
    const float* ng   = (const float*)d_in[1];
    const float* nb   = (const float*)d_in[2];
    const float* hW1  = (const float*)d_in[3];
    const float* hb1  = (const float*)d_in[4];
    const float* hlg  = (const float*)d_in[5];
    const float* hlb  = (const float*)d_in[6];
    const float* hW2  = (const float*)d_in[7];
    const float* hb2  = (const float*)d_in[8];
    const float* attr = (const float*)d_in[9];
    const float* dynm = (const float*)d_in[10];
    const float* gW   = (const float*)d_in[11];
    const float* gb   = (const float*)d_in[12];
    const float* oW1  = (const float*)d_in[13];
    const float* ob1  = (const float*)d_in[14];
    const float* olg  = (const float*)d_in[15];
    const float* olb  = (const float*)d_in[16];
    const float* oW2  = (const float*)d_in[17];
    const float* ob2  = (const float*)d_in[18];
    float* out = (float*)d_out;

    cudaFuncSetAttribute(k_head1_mma, cudaFuncAttributeMaxDynamicSharedMemorySize, K2_SMEM);
    cudaFuncSetAttribute(k_head2_mma, cudaFuncAttributeMaxDynamicSharedMemorySize, K3_SMEM);
    cudaFuncSetAttribute(k_out1_mma,  cudaFuncAttributeMaxDynamicSharedMemorySize, K4_SMEM);
    cudaFuncSetAttribute(k_out2_mma,  cudaFuncAttributeMaxDynamicSharedMemorySize, K5_SMEM);

    k_prep<<<4864, 256>>>(hW1, hW2, dynm, oW1, oW2);
    k_ln_gate<<<8192, 256>>>(x, ng, nb, gW, gb);

    dim3 gh(T_TOK / 64, 4);
    k_head1_mma<<<gh, 256, K2_SMEM>>>(hb1, hlg, hlb);
    k_head2_mma<<<gh, 256, K3_SMEM>>>(hb2, attr);

    k_out1_mma<<<T_TOK / 64, 512, K4_SMEM>>>(ob1, olg, olb);
    k_out2_mma<<<T_TOK / 64, 512, K5_SMEM>>>(ob2, out);
}